// round 6
// baseline (speedup 1.0000x reference)
#include <cuda_runtime.h>
#include <cuda_bf16.h>

#define N_NODES 100000
#define N_EDGES 3200000
#define IN_F    128
#define HID     3
#define OUT_F   4

// Kernel 1: every 5th block does degree atomics, the rest do the GEMV.
#define FUSED_BLOCKS 15625

// Kernel 2: persistent, co-resident (148 SMs x 8 blocks), software grid barrier
#define K2_BLOCKS  1184
#define K2_THREADS 256
#define K2_TOTAL   (K2_BLOCKS * K2_THREADS)   // 303,104 threads

// Scratch (device globals — zero-initialized at load; g_deg kept zero at entry
// by the scale phase resetting it every call)
__device__ float  g_deg[N_NODES];
__device__ float  g_dinv[N_NODES];
__device__ float4 g_sxw4[N_NODES];
__device__ float4 g_T4[N_NODES];

// Grid-barrier state. g_gen is monotonic across barriers AND graph replays;
// g_arrive is 0 whenever no barrier is in progress.
__device__ unsigned g_arrive;
__device__ volatile unsigned g_gen;

__device__ __forceinline__ void grid_barrier() {
    __threadfence();          // make this thread's prior writes globally visible
    __syncthreads();          // all block threads' writes ordered before leader arrives
    if (threadIdx.x == 0) {
        unsigned old = g_gen;                 // read generation BEFORE arriving
        if (atomicAdd(&g_arrive, 1u) == K2_BLOCKS - 1) {
            g_arrive = 0;                     // reset for next barrier
            __threadfence();
            g_gen = old + 1;                  // release
        } else {
            while (g_gen == old) { __nanosleep(40); }
            __threadfence();
        }
    }
    __syncthreads();
}

// ---------------------------------------------------------------------------
// 1) Fused deg + GEMV, role-interleaved by blockIdx % 5 so every scheduling
//    wave carries both atomic-bound and DRAM-bound work.
__global__ void k_deg_gemv(const int* __restrict__ col,
                           const float* __restrict__ x,
                           const float* __restrict__ W) {
    int q = blockIdx.x / 5;
    int r = blockIdx.x % 5;

    if (r == 0) {
        // ---- degree role (block q of 3125): 4 edges/thread, int4 col load
        int e = (q * blockDim.x + threadIdx.x) * 4;
        if (e + 3 < N_EDGES) {
            int4 c4 = *reinterpret_cast<const int4*>(col + e);
            if ((unsigned)c4.x < N_NODES) atomicAdd(&g_deg[c4.x], 1.0f);
            if ((unsigned)c4.y < N_NODES) atomicAdd(&g_deg[c4.y], 1.0f);
            if ((unsigned)c4.z < N_NODES) atomicAdd(&g_deg[c4.z], 1.0f);
            if ((unsigned)c4.w < N_NODES) atomicAdd(&g_deg[c4.w], 1.0f);
        } else {
            for (; e < N_EDGES; e++) {
                unsigned c = (unsigned)col[e];
                if (c < N_NODES) atomicAdd(&g_deg[c], 1.0f);
            }
        }
        return;
    }

    // ---- GEMV role: warp-per-node, xw = x[node] @ W (128 -> 3), unscaled
    __shared__ float sW[IN_F * HID];
    int tid = threadIdx.x;
    for (int i = tid; i < IN_F * HID; i += blockDim.x) sW[i] = W[i];
    __syncthreads();

    int g = q * 4 + (r - 1);
    int node = g * 8 + (tid >> 5);
    int lane = tid & 31;
    if (node >= N_NODES) return;

    const float4 xv = *reinterpret_cast<const float4*>(
        x + (size_t)node * IN_F + lane * 4);
    int k0 = lane * 4;
    const float* w0 = &sW[(k0 + 0) * HID];
    const float* w1 = &sW[(k0 + 1) * HID];
    const float* w2 = &sW[(k0 + 2) * HID];
    const float* w3 = &sW[(k0 + 3) * HID];

    float a0 = xv.x * w0[0] + xv.y * w1[0] + xv.z * w2[0] + xv.w * w3[0];
    float a1 = xv.x * w0[1] + xv.y * w1[1] + xv.z * w2[1] + xv.w * w3[1];
    float a2 = xv.x * w0[2] + xv.y * w1[2] + xv.z * w2[2] + xv.w * w3[2];

    #pragma unroll
    for (int off = 16; off > 0; off >>= 1) {
        a0 += __shfl_down_sync(0xffffffffu, a0, off);
        a1 += __shfl_down_sync(0xffffffffu, a1, off);
        a2 += __shfl_down_sync(0xffffffffu, a2, off);
    }

    if (lane == 0) {
        g_sxw4[node] = make_float4(a0, a1, a2, 0.0f);
    }
}

// ---------------------------------------------------------------------------
// 2) Persistent kernel: scale -> barrier -> edge scatter -> barrier -> final
__global__ void __launch_bounds__(K2_THREADS, 8)
k_main(const int* __restrict__ ei,
       const float* __restrict__ b,
       const float* __restrict__ Wout,
       const float* __restrict__ bout,
       float* __restrict__ out) {
    const unsigned gtid = blockIdx.x * K2_THREADS + threadIdx.x;

    // ---- Phase 1: scale.  dinv = rsqrt(deg+1); sxw *= dinv; T = sxw (self
    //      loop); reset deg for next replay.  25,000 float4-groups.
    {
        unsigned i = gtid * 4;
        if (i + 3 < N_NODES) {           // N_NODES % 4 == 0, exact
            float4 d4 = *reinterpret_cast<float4*>(&g_deg[i]);
            float4 dv;
            dv.x = rsqrtf(d4.x + 1.0f);
            dv.y = rsqrtf(d4.y + 1.0f);
            dv.z = rsqrtf(d4.z + 1.0f);
            dv.w = rsqrtf(d4.w + 1.0f);
            *reinterpret_cast<float4*>(&g_deg[i])  = make_float4(0.f, 0.f, 0.f, 0.f);
            *reinterpret_cast<float4*>(&g_dinv[i]) = dv;

            float4 s0 = g_sxw4[i + 0];
            float4 s1 = g_sxw4[i + 1];
            float4 s2 = g_sxw4[i + 2];
            float4 s3 = g_sxw4[i + 3];
            s0.x *= dv.x; s0.y *= dv.x; s0.z *= dv.x;
            s1.x *= dv.y; s1.y *= dv.y; s1.z *= dv.y;
            s2.x *= dv.z; s2.y *= dv.z; s2.z *= dv.z;
            s3.x *= dv.w; s3.y *= dv.w; s3.z *= dv.w;
            g_sxw4[i + 0] = s0;  g_T4[i + 0] = s0;
            g_sxw4[i + 1] = s1;  g_T4[i + 1] = s1;
            g_sxw4[i + 2] = s2;  g_T4[i + 2] = s2;
            g_sxw4[i + 3] = s3;  g_T4[i + 3] = s3;
        }
    }

    grid_barrier();

    // ---- Phase 2: edge scatter.  800,000 chunks of 4 edges (exact), strided.
    {
        const unsigned NCHUNK = N_EDGES / 4;
        for (unsigned c = gtid; c < NCHUNK; c += K2_TOTAL) {
            unsigned e = c * 4;
            int4 r4 = *reinterpret_cast<const int4*>(ei + e);
            int4 c4 = *reinterpret_cast<const int4*>(ei + N_EDGES + e);
            if ((unsigned)r4.x < N_NODES && (unsigned)c4.x < N_NODES)
                atomicAdd(&g_T4[c4.x], g_sxw4[r4.x]);
            if ((unsigned)r4.y < N_NODES && (unsigned)c4.y < N_NODES)
                atomicAdd(&g_T4[c4.y], g_sxw4[r4.y]);
            if ((unsigned)r4.z < N_NODES && (unsigned)c4.z < N_NODES)
                atomicAdd(&g_T4[c4.z], g_sxw4[r4.z]);
            if ((unsigned)r4.w < N_NODES && (unsigned)c4.w < N_NODES)
                atomicAdd(&g_T4[c4.w], g_sxw4[r4.w]);
        }
    }

    grid_barrier();

    // ---- Phase 3: final.  h = relu(dinv*T + b); z = h @ Wout + bout.
    for (unsigned i = gtid; i < N_NODES; i += K2_TOTAL) {
        float dinv = g_dinv[i];
        float4 tv = g_T4[i];
        float h0 = fmaxf(tv.x * dinv + __ldg(&b[0]), 0.0f);
        float h1 = fmaxf(tv.y * dinv + __ldg(&b[1]), 0.0f);
        float h2 = fmaxf(tv.z * dinv + __ldg(&b[2]), 0.0f);

        unsigned base = i * HID;
        out[base + 0] = h0;
        out[base + 1] = h1;
        out[base + 2] = h2;

        float4 z;
        z.x = h0 * __ldg(&Wout[0]) + h1 * __ldg(&Wout[4]) + h2 * __ldg(&Wout[8])  + __ldg(&bout[0]);
        z.y = h0 * __ldg(&Wout[1]) + h1 * __ldg(&Wout[5]) + h2 * __ldg(&Wout[9])  + __ldg(&bout[1]);
        z.z = h0 * __ldg(&Wout[2]) + h1 * __ldg(&Wout[6]) + h2 * __ldg(&Wout[10]) + __ldg(&bout[2]);
        z.w = h0 * __ldg(&Wout[3]) + h1 * __ldg(&Wout[7]) + h2 * __ldg(&Wout[11]) + __ldg(&bout[3]);
        *reinterpret_cast<float4*>(out + (size_t)N_NODES * HID + (size_t)i * OUT_F) = z;
    }
}

extern "C" void kernel_launch(void* const* d_in, const int* in_sizes, int n_in,
                              void* d_out, int out_size) {
    // Bind inputs by element count (robust to ordering):
    // x=12,800,000  edge_index=6,400,000  W=384  b=3  Wout=12  bout=4
    const float* x    = nullptr;
    const int*   ei   = nullptr;
    const float* W    = nullptr;
    const float* b    = nullptr;
    const float* Wout = nullptr;
    const float* bout = nullptr;
    for (int i = 0; i < n_in; i++) {
        switch (in_sizes[i]) {
            case 12800000: x    = (const float*)d_in[i]; break;
            case 6400000:  ei   = (const int*)  d_in[i]; break;
            case 384:      W    = (const float*)d_in[i]; break;
            case 3:        b    = (const float*)d_in[i]; break;
            case 12:       Wout = (const float*)d_in[i]; break;
            case 4:        bout = (const float*)d_in[i]; break;
            default: break;
        }
    }

    float* out = (float*)d_out;

    k_deg_gemv<<<FUSED_BLOCKS, 256>>>(ei + N_EDGES, x, W);
    k_main<<<K2_BLOCKS, K2_THREADS>>>(ei, b, Wout, bout, out);
}

// round 7
// speedup vs baseline: 1.1368x; 1.1368x over previous
#include <cuda_runtime.h>
#include <cuda_bf16.h>

#define N_NODES 100000
#define N_EDGES 3200000
#define IN_F    128
#define HID     3
#define OUT_F   4

// Kernel 1: every 5th block does degree atomics, the rest do the GEMV.
#define FUSED_BLOCKS 15625

// Scratch (device globals — zero-initialized at load; g_deg kept zero at entry
// by k_scale resetting it every call)
__device__ float  g_deg[N_NODES];
__device__ float  g_dinv[N_NODES];
__device__ float4 g_sxw4[N_NODES];
__device__ float4 g_T4[N_NODES];

// ---------------------------------------------------------------------------
// 1) Fused deg + GEMV, role-interleaved by blockIdx % 5 so every scheduling
//    wave carries both atomic-bound (LSU/LTS) and DRAM-bound work.
__global__ void k_deg_gemv(const int* __restrict__ col,
                           const float* __restrict__ x,
                           const float* __restrict__ W) {
    int q = blockIdx.x / 5;
    int r = blockIdx.x % 5;

    if (r == 0) {
        // ---- degree role (block q of 3125): 4 edges/thread, int4 col load
        int e = (q * blockDim.x + threadIdx.x) * 4;
        if (e + 3 < N_EDGES) {
            int4 c4 = *reinterpret_cast<const int4*>(col + e);
            if ((unsigned)c4.x < N_NODES) atomicAdd(&g_deg[c4.x], 1.0f);
            if ((unsigned)c4.y < N_NODES) atomicAdd(&g_deg[c4.y], 1.0f);
            if ((unsigned)c4.z < N_NODES) atomicAdd(&g_deg[c4.z], 1.0f);
            if ((unsigned)c4.w < N_NODES) atomicAdd(&g_deg[c4.w], 1.0f);
        } else {
            for (; e < N_EDGES; e++) {
                unsigned c = (unsigned)col[e];
                if (c < N_NODES) atomicAdd(&g_deg[c], 1.0f);
            }
        }
        return;
    }

    // ---- GEMV role: warp-per-node, xw = x[node] @ W (128 -> 3), unscaled
    __shared__ float sW[IN_F * HID];
    int tid = threadIdx.x;
    for (int i = tid; i < IN_F * HID; i += blockDim.x) sW[i] = W[i];
    __syncthreads();

    int g = q * 4 + (r - 1);
    int node = g * 8 + (tid >> 5);
    int lane = tid & 31;
    if (node >= N_NODES) return;

    const float4 xv = *reinterpret_cast<const float4*>(
        x + (size_t)node * IN_F + lane * 4);
    int k0 = lane * 4;
    const float* w0 = &sW[(k0 + 0) * HID];
    const float* w1 = &sW[(k0 + 1) * HID];
    const float* w2 = &sW[(k0 + 2) * HID];
    const float* w3 = &sW[(k0 + 3) * HID];

    float a0 = xv.x * w0[0] + xv.y * w1[0] + xv.z * w2[0] + xv.w * w3[0];
    float a1 = xv.x * w0[1] + xv.y * w1[1] + xv.z * w2[1] + xv.w * w3[1];
    float a2 = xv.x * w0[2] + xv.y * w1[2] + xv.z * w2[2] + xv.w * w3[2];

    #pragma unroll
    for (int off = 16; off > 0; off >>= 1) {
        a0 += __shfl_down_sync(0xffffffffu, a0, off);
        a1 += __shfl_down_sync(0xffffffffu, a1, off);
        a2 += __shfl_down_sync(0xffffffffu, a2, off);
    }

    if (lane == 0) {
        g_sxw4[node] = make_float4(a0, a1, a2, 0.0f);
    }
}

// ---------------------------------------------------------------------------
// 2) Per node (4 nodes/thread, vectorized): dinv = rsqrt(deg+1); scale sxw4;
//    seed T4 with self-loop term; reset g_deg for next replay.
__global__ void k_scale() {
    int t = blockIdx.x * blockDim.x + threadIdx.x;
    int i = t * 4;
    if (i + 3 >= N_NODES) {
        for (; i < N_NODES; i++) {
            float dinv = rsqrtf(g_deg[i] + 1.0f);
            g_deg[i] = 0.0f;
            g_dinv[i] = dinv;
            float4 s = g_sxw4[i];
            s.x *= dinv; s.y *= dinv; s.z *= dinv;
            g_sxw4[i] = s;
            g_T4[i]   = s;
        }
        return;
    }
    float4 d4 = *reinterpret_cast<float4*>(&g_deg[i]);
    float4 dv;
    dv.x = rsqrtf(d4.x + 1.0f);
    dv.y = rsqrtf(d4.y + 1.0f);
    dv.z = rsqrtf(d4.z + 1.0f);
    dv.w = rsqrtf(d4.w + 1.0f);
    *reinterpret_cast<float4*>(&g_deg[i])  = make_float4(0.f, 0.f, 0.f, 0.f);
    *reinterpret_cast<float4*>(&g_dinv[i]) = dv;

    float4 s0 = g_sxw4[i + 0];
    float4 s1 = g_sxw4[i + 1];
    float4 s2 = g_sxw4[i + 2];
    float4 s3 = g_sxw4[i + 3];
    s0.x *= dv.x; s0.y *= dv.x; s0.z *= dv.x;
    s1.x *= dv.y; s1.y *= dv.y; s1.z *= dv.y;
    s2.x *= dv.z; s2.y *= dv.z; s2.z *= dv.z;
    s3.x *= dv.w; s3.y *= dv.w; s3.z *= dv.w;
    g_sxw4[i + 0] = s0;  g_T4[i + 0] = s0;
    g_sxw4[i + 1] = s1;  g_T4[i + 1] = s1;
    g_sxw4[i + 2] = s2;  g_T4[i + 2] = s2;
    g_sxw4[i + 3] = s3;  g_T4[i + 3] = s3;
}

// ---------------------------------------------------------------------------
// 3) Per edge: T4[col] += sxw4[row].  4 edges/thread, int4 index loads,
//    LDG.128 gather + RED.128 per edge.  (At the L1tex-wavefront floor.)
__global__ void k_edge(const int* __restrict__ ei) {
    int e = (blockIdx.x * blockDim.x + threadIdx.x) * 4;
    if (e + 3 < N_EDGES) {
        int4 r4 = *reinterpret_cast<const int4*>(ei + e);
        int4 c4 = *reinterpret_cast<const int4*>(ei + N_EDGES + e);
        if ((unsigned)r4.x < N_NODES && (unsigned)c4.x < N_NODES)
            atomicAdd(&g_T4[c4.x], g_sxw4[r4.x]);
        if ((unsigned)r4.y < N_NODES && (unsigned)c4.y < N_NODES)
            atomicAdd(&g_T4[c4.y], g_sxw4[r4.y]);
        if ((unsigned)r4.z < N_NODES && (unsigned)c4.z < N_NODES)
            atomicAdd(&g_T4[c4.z], g_sxw4[r4.z]);
        if ((unsigned)r4.w < N_NODES && (unsigned)c4.w < N_NODES)
            atomicAdd(&g_T4[c4.w], g_sxw4[r4.w]);
    } else {
        for (; e < N_EDGES; e++) {
            unsigned r = (unsigned)ei[e];
            unsigned c = (unsigned)ei[N_EDGES + e];
            if (r < N_NODES && c < N_NODES)
                atomicAdd(&g_T4[c], g_sxw4[r]);
        }
    }
}

// ---------------------------------------------------------------------------
// 4) Epilogue, role-split over 2*N_NODES threads for 2x concurrency:
//    thread i < N:   compute h[i], store 3 floats
//    thread i >= N:  recompute h[i-N], compute z, store one float4
__global__ void k_final(const float* __restrict__ b,
                        const float* __restrict__ Wout,
                        const float* __restrict__ bout,
                        float* __restrict__ out) {
    unsigned t = blockIdx.x * blockDim.x + threadIdx.x;
    if (t >= 2u * N_NODES) return;
    unsigned i   = (t < N_NODES) ? t : t - N_NODES;

    float dinv = g_dinv[i];
    float4 tv  = g_T4[i];
    float h0 = fmaxf(tv.x * dinv + __ldg(&b[0]), 0.0f);
    float h1 = fmaxf(tv.y * dinv + __ldg(&b[1]), 0.0f);
    float h2 = fmaxf(tv.z * dinv + __ldg(&b[2]), 0.0f);

    if (t < N_NODES) {
        unsigned base = i * HID;
        out[base + 0] = h0;
        out[base + 1] = h1;
        out[base + 2] = h2;
    } else {
        float4 z;
        z.x = h0 * __ldg(&Wout[0]) + h1 * __ldg(&Wout[4]) + h2 * __ldg(&Wout[8])  + __ldg(&bout[0]);
        z.y = h0 * __ldg(&Wout[1]) + h1 * __ldg(&Wout[5]) + h2 * __ldg(&Wout[9])  + __ldg(&bout[1]);
        z.z = h0 * __ldg(&Wout[2]) + h1 * __ldg(&Wout[6]) + h2 * __ldg(&Wout[10]) + __ldg(&bout[2]);
        z.w = h0 * __ldg(&Wout[3]) + h1 * __ldg(&Wout[7]) + h2 * __ldg(&Wout[11]) + __ldg(&bout[3]);
        *reinterpret_cast<float4*>(out + (size_t)N_NODES * HID + (size_t)i * OUT_F) = z;
    }
}

extern "C" void kernel_launch(void* const* d_in, const int* in_sizes, int n_in,
                              void* d_out, int out_size) {
    // Bind inputs by element count (robust to ordering):
    // x=12,800,000  edge_index=6,400,000  W=384  b=3  Wout=12  bout=4
    const float* x    = nullptr;
    const int*   ei   = nullptr;
    const float* W    = nullptr;
    const float* b    = nullptr;
    const float* Wout = nullptr;
    const float* bout = nullptr;
    for (int i = 0; i < n_in; i++) {
        switch (in_sizes[i]) {
            case 12800000: x    = (const float*)d_in[i]; break;
            case 6400000:  ei   = (const int*)  d_in[i]; break;
            case 384:      W    = (const float*)d_in[i]; break;
            case 3:        b    = (const float*)d_in[i]; break;
            case 12:       Wout = (const float*)d_in[i]; break;
            case 4:        bout = (const float*)d_in[i]; break;
            default: break;
        }
    }

    float* out = (float*)d_out;

    const int T = 256;
    k_deg_gemv<<<FUSED_BLOCKS, T>>>(ei + N_EDGES, x, W);
    k_scale<<<((N_NODES / 4) + T - 1) / T, T>>>();
    k_edge<<<((N_EDGES / 4) + T - 1) / T, T>>>(ei);
    k_final<<<((2 * N_NODES) + T - 1) / T, T>>>(b, Wout, bout, out);
}

// round 8
// speedup vs baseline: 1.1416x; 1.0043x over previous
#include <cuda_runtime.h>
#include <cuda_bf16.h>

#define N_NODES 100000
#define N_EDGES 3200000
#define IN_F    128
#define HID     3
#define OUT_F   4

// Kernel 1: every 5th block does degree atomics, the rest do the GEMV.
#define FUSED_BLOCKS 15625

// Scratch (device globals — zero-initialized at load; g_deg kept zero at entry
// by k_scale resetting it every call)
__device__ float  g_deg[N_NODES];
__device__ float  g_dinv[N_NODES];
__device__ float4 g_sxw4[N_NODES];
__device__ float4 g_T4[N_NODES];

// ---------------------------------------------------------------------------
// 1) Fused deg + GEMV, role-interleaved by blockIdx % 5.
//    PDL: all input loads (edge col / x / W) happen pre-sync so they overlap
//    the previous replay's tail; all writes to g_* are post-sync.
__global__ void k_deg_gemv(const int* __restrict__ col,
                           const float* __restrict__ x,
                           const float* __restrict__ W) {
    int q = blockIdx.x / 5;
    int r = blockIdx.x % 5;

    if (r == 0) {
        // ---- degree role (block q of 3125): 4 edges/thread, int4 col load
        int e = (q * blockDim.x + threadIdx.x) * 4;
        int4 c4 = make_int4(-1, -1, -1, -1);
        if (e + 3 < N_EDGES)
            c4 = *reinterpret_cast<const int4*>(col + e);
        cudaGridDependencySynchronize();
        if ((unsigned)c4.x < N_NODES) atomicAdd(&g_deg[c4.x], 1.0f);
        if ((unsigned)c4.y < N_NODES) atomicAdd(&g_deg[c4.y], 1.0f);
        if ((unsigned)c4.z < N_NODES) atomicAdd(&g_deg[c4.z], 1.0f);
        if ((unsigned)c4.w < N_NODES) atomicAdd(&g_deg[c4.w], 1.0f);
        cudaTriggerProgrammaticLaunchCompletion();
        return;
    }

    // ---- GEMV role: warp-per-node, xw = x[node] @ W (128 -> 3), unscaled
    __shared__ float sW[IN_F * HID];
    int tid = threadIdx.x;
    for (int i = tid; i < IN_F * HID; i += blockDim.x) sW[i] = W[i];
    __syncthreads();

    int g = q * 4 + (r - 1);
    int node = g * 8 + (tid >> 5);
    int lane = tid & 31;
    if (node >= N_NODES) {           // never taken (100000 % 8 == 0), safety
        cudaGridDependencySynchronize();
        cudaTriggerProgrammaticLaunchCompletion();
        return;
    }

    const float4 xv = *reinterpret_cast<const float4*>(
        x + (size_t)node * IN_F + lane * 4);
    int k0 = lane * 4;
    const float* w0 = &sW[(k0 + 0) * HID];
    const float* w1 = &sW[(k0 + 1) * HID];
    const float* w2 = &sW[(k0 + 2) * HID];
    const float* w3 = &sW[(k0 + 3) * HID];

    float a0 = xv.x * w0[0] + xv.y * w1[0] + xv.z * w2[0] + xv.w * w3[0];
    float a1 = xv.x * w0[1] + xv.y * w1[1] + xv.z * w2[1] + xv.w * w3[1];
    float a2 = xv.x * w0[2] + xv.y * w1[2] + xv.z * w2[2] + xv.w * w3[2];

    #pragma unroll
    for (int off = 16; off > 0; off >>= 1) {
        a0 += __shfl_down_sync(0xffffffffu, a0, off);
        a1 += __shfl_down_sync(0xffffffffu, a1, off);
        a2 += __shfl_down_sync(0xffffffffu, a2, off);
    }

    cudaGridDependencySynchronize();   // prior replay's k_edge readers done
    if (lane == 0) {
        g_sxw4[node] = make_float4(a0, a1, a2, 0.0f);
    }
    cudaTriggerProgrammaticLaunchCompletion();
}

// ---------------------------------------------------------------------------
// 2) Per node (4 nodes/thread, vectorized): dinv = rsqrt(deg+1); scale sxw4;
//    seed T4 with self-loop term; reset g_deg for next replay.
__global__ void k_scale() {
    cudaGridDependencySynchronize();   // needs deg + sxw4 complete
    int t = blockIdx.x * blockDim.x + threadIdx.x;
    int i = t * 4;
    if (i + 3 < N_NODES) {             // N_NODES % 4 == 0 -> exact
        float4 d4 = *reinterpret_cast<float4*>(&g_deg[i]);
        float4 dv;
        dv.x = rsqrtf(d4.x + 1.0f);
        dv.y = rsqrtf(d4.y + 1.0f);
        dv.z = rsqrtf(d4.z + 1.0f);
        dv.w = rsqrtf(d4.w + 1.0f);
        *reinterpret_cast<float4*>(&g_deg[i])  = make_float4(0.f, 0.f, 0.f, 0.f);
        *reinterpret_cast<float4*>(&g_dinv[i]) = dv;

        float4 s0 = g_sxw4[i + 0];
        float4 s1 = g_sxw4[i + 1];
        float4 s2 = g_sxw4[i + 2];
        float4 s3 = g_sxw4[i + 3];
        s0.x *= dv.x; s0.y *= dv.x; s0.z *= dv.x;
        s1.x *= dv.y; s1.y *= dv.y; s1.z *= dv.y;
        s2.x *= dv.z; s2.y *= dv.z; s2.z *= dv.z;
        s3.x *= dv.w; s3.y *= dv.w; s3.z *= dv.w;
        g_sxw4[i + 0] = s0;  g_T4[i + 0] = s0;
        g_sxw4[i + 1] = s1;  g_T4[i + 1] = s1;
        g_sxw4[i + 2] = s2;  g_T4[i + 2] = s2;
        g_sxw4[i + 3] = s3;  g_T4[i + 3] = s3;
    }
    cudaTriggerProgrammaticLaunchCompletion();
}

// ---------------------------------------------------------------------------
// 3) Per edge: T4[col] += sxw4[row].  4 edges/thread, int4 index loads
//    (pre-sync: pure input), LDG.128 gather + RED.128 per edge.
__global__ void k_edge(const int* __restrict__ ei) {
    int e = (blockIdx.x * blockDim.x + threadIdx.x) * 4;
    int4 r4 = make_int4(-1, -1, -1, -1);
    int4 c4 = make_int4(-1, -1, -1, -1);
    if (e + 3 < N_EDGES) {             // N_EDGES % 4 == 0 -> exact
        r4 = *reinterpret_cast<const int4*>(ei + e);
        c4 = *reinterpret_cast<const int4*>(ei + N_EDGES + e);
    }
    cudaGridDependencySynchronize();   // sxw4 / T4 ready
    if ((unsigned)r4.x < N_NODES && (unsigned)c4.x < N_NODES)
        atomicAdd(&g_T4[c4.x], g_sxw4[r4.x]);
    if ((unsigned)r4.y < N_NODES && (unsigned)c4.y < N_NODES)
        atomicAdd(&g_T4[c4.y], g_sxw4[r4.y]);
    if ((unsigned)r4.z < N_NODES && (unsigned)c4.z < N_NODES)
        atomicAdd(&g_T4[c4.z], g_sxw4[r4.z]);
    if ((unsigned)r4.w < N_NODES && (unsigned)c4.w < N_NODES)
        atomicAdd(&g_T4[c4.w], g_sxw4[r4.w]);
    cudaTriggerProgrammaticLaunchCompletion();
}

// ---------------------------------------------------------------------------
// 4) Epilogue, role-split over 2*N_NODES threads:
//    thread t < N:  compute h[t], store 3 floats
//    thread t >= N: recompute h[t-N], compute z, store one float4
//    Constants loaded pre-sync (pure inputs).
__global__ void k_final(const float* __restrict__ b,
                        const float* __restrict__ Wout,
                        const float* __restrict__ bout,
                        float* __restrict__ out) {
    unsigned t = blockIdx.x * blockDim.x + threadIdx.x;
    bool zrole = (t >= N_NODES);
    unsigned i = zrole ? t - N_NODES : t;
    bool valid = (t < 2u * N_NODES);

    float b0 = __ldg(&b[0]), b1 = __ldg(&b[1]), b2 = __ldg(&b[2]);
    float w00 = 0, w01 = 0, w02 = 0, w03 = 0;
    float w10 = 0, w11 = 0, w12 = 0, w13 = 0;
    float w20 = 0, w21 = 0, w22 = 0, w23 = 0;
    float zb0 = 0, zb1 = 0, zb2 = 0, zb3 = 0;
    if (zrole) {
        w00 = __ldg(&Wout[0]);  w01 = __ldg(&Wout[1]);  w02 = __ldg(&Wout[2]);  w03 = __ldg(&Wout[3]);
        w10 = __ldg(&Wout[4]);  w11 = __ldg(&Wout[5]);  w12 = __ldg(&Wout[6]);  w13 = __ldg(&Wout[7]);
        w20 = __ldg(&Wout[8]);  w21 = __ldg(&Wout[9]);  w22 = __ldg(&Wout[10]); w23 = __ldg(&Wout[11]);
        zb0 = __ldg(&bout[0]);  zb1 = __ldg(&bout[1]);  zb2 = __ldg(&bout[2]);  zb3 = __ldg(&bout[3]);
    }

    cudaGridDependencySynchronize();   // T4 aggregation complete
    if (!valid) return;

    float dinv = g_dinv[i];
    float4 tv  = g_T4[i];
    float h0 = fmaxf(tv.x * dinv + b0, 0.0f);
    float h1 = fmaxf(tv.y * dinv + b1, 0.0f);
    float h2 = fmaxf(tv.z * dinv + b2, 0.0f);

    if (!zrole) {
        unsigned base = i * HID;
        out[base + 0] = h0;
        out[base + 1] = h1;
        out[base + 2] = h2;
    } else {
        float4 z;
        z.x = h0 * w00 + h1 * w10 + h2 * w20 + zb0;
        z.y = h0 * w01 + h1 * w11 + h2 * w21 + zb1;
        z.z = h0 * w02 + h1 * w12 + h2 * w22 + zb2;
        z.w = h0 * w03 + h1 * w13 + h2 * w23 + zb3;
        *reinterpret_cast<float4*>(out + (size_t)N_NODES * HID + (size_t)i * OUT_F) = z;
    }
}

// ---------------------------------------------------------------------------
static inline void launch_pdl(void* fn, dim3 grid, dim3 block,
                              void** args) {
    cudaLaunchConfig_t cfg = {};
    cfg.gridDim = grid;
    cfg.blockDim = block;
    cfg.dynamicSmemBytes = 0;
    cfg.stream = 0;   // capturing (default) stream
    cudaLaunchAttribute attr[1];
    attr[0].id = cudaLaunchAttributeProgrammaticStreamSerialization;
    attr[0].val.programmaticStreamSerializationAllowed = 1;
    cfg.attrs = attr;
    cfg.numAttrs = 1;
    cudaLaunchKernelExC(&cfg, fn, args);
}

extern "C" void kernel_launch(void* const* d_in, const int* in_sizes, int n_in,
                              void* d_out, int out_size) {
    // Bind inputs by element count (robust to ordering):
    // x=12,800,000  edge_index=6,400,000  W=384  b=3  Wout=12  bout=4
    const float* x    = nullptr;
    const int*   ei   = nullptr;
    const float* W    = nullptr;
    const float* b    = nullptr;
    const float* Wout = nullptr;
    const float* bout = nullptr;
    for (int i = 0; i < n_in; i++) {
        switch (in_sizes[i]) {
            case 12800000: x    = (const float*)d_in[i]; break;
            case 6400000:  ei   = (const int*)  d_in[i]; break;
            case 384:      W    = (const float*)d_in[i]; break;
            case 3:        b    = (const float*)d_in[i]; break;
            case 12:       Wout = (const float*)d_in[i]; break;
            case 4:        bout = (const float*)d_in[i]; break;
            default: break;
        }
    }

    float* out = (float*)d_out;
    const int T = 256;

    const int* col = ei + N_EDGES;
    {
        void* args[] = { (void*)&col, (void*)&x, (void*)&W };
        launch_pdl((void*)k_deg_gemv, dim3(FUSED_BLOCKS), dim3(T), args);
    }
    {
        void* args[] = { };
        cudaLaunchConfig_t cfg = {};
        cfg.gridDim = dim3((N_NODES / 4 + T - 1) / T);
        cfg.blockDim = dim3(T);
        cfg.stream = 0;
        cudaLaunchAttribute attr[1];
        attr[0].id = cudaLaunchAttributeProgrammaticStreamSerialization;
        attr[0].val.programmaticStreamSerializationAllowed = 1;
        cfg.attrs = attr;
        cfg.numAttrs = 1;
        cudaLaunchKernelExC(&cfg, (void*)k_scale, args);
    }
    {
        void* args[] = { (void*)&ei };
        launch_pdl((void*)k_edge, dim3((N_EDGES / 4) / T), dim3(T), args);
    }
    {
        void* args[] = { (void*)&b, (void*)&Wout, (void*)&bout, (void*)&out };
        launch_pdl((void*)k_final, dim3((2 * N_NODES + T - 1) / T), dim3(T), args);
    }
}